// round 4
// baseline (speedup 1.0000x reference)
#include <cuda_runtime.h>
#include <cstdint>

// Sparse dropout: out_values[i] = mask[i] ? values[i] * (1/KPROB) : 0
// KPROB = 0.5 -> scale = 2.0f
//
// Harness marshals all inputs to {float32, int32, bfloat16}:
//   d_in[0]: indices  int32 (converted from int64), 2*NNZ elements
//   d_in[1]: values   float32, NNZ elements
//   d_in[2]: mask     int32 (converted from bool, 0/1), NNZ elements
//
// Output (float32), dispatch on out_size:
//   out_size >= 3*NNZ -> [indices cast to f32 (2*NNZ)] ++ [dropout values (NNZ)]
//   else              -> just the dropout'd values (NNZ)

static constexpr float SCALE = 2.0f;  // 1 / KPROB, KPROB = 0.5

// Dropout: 4 floats + 4 int32 masks per thread (16B loads, 16B store).
__global__ void __launch_bounds__(256)
dropout_vec4(const float4* __restrict__ vals,
             const int4* __restrict__ mask4,
             float4* __restrict__ out,
             int n4) {
    int stride = gridDim.x * blockDim.x;
    for (int i = blockIdx.x * blockDim.x + threadIdx.x; i < n4; i += stride) {
        float4 v = vals[i];
        int4 m = mask4[i];
        float4 o;
        o.x = m.x ? v.x * SCALE : 0.0f;
        o.y = m.y ? v.y * SCALE : 0.0f;
        o.z = m.z ? v.z * SCALE : 0.0f;
        o.w = m.w ? v.w * SCALE : 0.0f;
        out[i] = o;
    }
}

// Scalar dropout tail (n not divisible by 4).
__global__ void __launch_bounds__(256)
dropout_tail(const float* __restrict__ vals,
             const int* __restrict__ mask,
             float* __restrict__ out,
             int start, int n) {
    int stride = gridDim.x * blockDim.x;
    for (int i = start + blockIdx.x * blockDim.x + threadIdx.x; i < n; i += stride) {
        out[i] = mask[i] ? vals[i] * SCALE : 0.0f;
    }
}

// Cast int32 indices -> float32, 4 per thread (16B load, 16B store).
__global__ void __launch_bounds__(256)
idx_cast_vec4(const int4* __restrict__ idx,
              float4* __restrict__ out,
              int n4) {
    int stride = gridDim.x * blockDim.x;
    for (int i = blockIdx.x * blockDim.x + threadIdx.x; i < n4; i += stride) {
        int4 v = idx[i];
        out[i] = make_float4((float)v.x, (float)v.y, (float)v.z, (float)v.w);
    }
}

__global__ void __launch_bounds__(256)
idx_cast_tail(const int* __restrict__ idx,
              float* __restrict__ out,
              int start, int n) {
    int stride = gridDim.x * blockDim.x;
    for (int i = start + blockIdx.x * blockDim.x + threadIdx.x; i < n; i += stride) {
        out[i] = (float)idx[i];
    }
}

static inline int grid_for(int n, int tpb) {
    long long g = ((long long)n + tpb - 1) / tpb;
    if (g > 1048576) g = 1048576;
    if (g < 1) g = 1;
    return (int)g;
}

extern "C" void kernel_launch(void* const* d_in, const int* in_sizes, int n_in,
                              void* d_out, int out_size) {
    const int*   indices = (const int*)d_in[0];
    const float* values  = (const float*)d_in[1];
    const int*   mask    = (const int*)d_in[2];

    const int n_idx = in_sizes[0];   // 2 * NNZ
    const int nnz   = in_sizes[1];   // NNZ

    const int TPB = 256;

    float* out_values = (float*)d_out;

    if (out_size >= n_idx + nnz) {
        // Combined layout: [indices as f32 (n_idx)] ++ [dropout values (nnz)].
        float* out_idx = (float*)d_out;
        out_values = (float*)d_out + n_idx;

        int n4i = n_idx / 4;
        if (n4i > 0) {
            idx_cast_vec4<<<grid_for(n4i, TPB), TPB>>>(
                (const int4*)indices, (float4*)out_idx, n4i);
        }
        int rem_start = n4i * 4;
        if (rem_start < n_idx) {
            idx_cast_tail<<<1, TPB>>>(indices, out_idx, rem_start, n_idx);
        }
    }

    int n4 = nnz / 4;
    if (n4 > 0) {
        dropout_vec4<<<grid_for(n4, TPB), TPB>>>(
            (const float4*)values, (const int4*)mask,
            (float4*)out_values, n4);
    }
    int tail_start = n4 * 4;
    if (tail_start < nnz) {
        dropout_tail<<<1, TPB>>>(values, mask, out_values, tail_start, nnz);
    }
}

// round 6
// speedup vs baseline: 1.0303x; 1.0303x over previous
#include <cuda_runtime.h>
#include <cstdint>

// Sparse dropout: out_values[i] = mask[i] ? values[i] * (1/KPROB) : 0
// KPROB = 0.5 -> scale = 2.0f
//
// Inputs (harness-marshaled):
//   d_in[0]: indices  int32, 2*NNZ elements
//   d_in[1]: values   float32, NNZ elements
//   d_in[2]: mask     int32 (0/1), NNZ elements
//
// Output (float32): [indices cast to f32 (2*NNZ)] ++ [dropout values (NNZ)]
// (falls back to values-only if out_size < 3*NNZ)

static constexpr float SCALE = 2.0f;  // 1 / KPROB

// Dropout, 2 strided float4+int4 pairs per thread (4 independent 16B loads
// front-batched -> MLP=4), streaming cache hints (single-touch data).
__global__ void __launch_bounds__(256)
dropout_vec4x2(const float4* __restrict__ vals,
               const int4* __restrict__ mask4,
               float4* __restrict__ out,
               int half) {
    int i = blockIdx.x * blockDim.x + threadIdx.x;
    if (i < half) {
        float4 v0 = __ldcs(&vals[i]);
        float4 v1 = __ldcs(&vals[i + half]);
        int4   m0 = __ldcs(&mask4[i]);
        int4   m1 = __ldcs(&mask4[i + half]);
        float4 o0, o1;
        o0.x = m0.x ? v0.x * SCALE : 0.0f;
        o0.y = m0.y ? v0.y * SCALE : 0.0f;
        o0.z = m0.z ? v0.z * SCALE : 0.0f;
        o0.w = m0.w ? v0.w * SCALE : 0.0f;
        o1.x = m1.x ? v1.x * SCALE : 0.0f;
        o1.y = m1.y ? v1.y * SCALE : 0.0f;
        o1.z = m1.z ? v1.z * SCALE : 0.0f;
        o1.w = m1.w ? v1.w * SCALE : 0.0f;
        __stcs(&out[i], o0);
        __stcs(&out[i + half], o1);
    }
}

// Scalar dropout tail.
__global__ void __launch_bounds__(256)
dropout_tail(const float* __restrict__ vals,
             const int* __restrict__ mask,
             float* __restrict__ out,
             int start, int n) {
    int i = start + blockIdx.x * blockDim.x + threadIdx.x;
    if (i < n) {
        out[i] = mask[i] ? vals[i] * SCALE : 0.0f;
    }
}

// Index cast, 2 strided int4 -> float4 per thread (MLP=2).
__global__ void __launch_bounds__(256)
idx_cast_vec4x2(const int4* __restrict__ idx,
                float4* __restrict__ out,
                int half) {
    int i = blockIdx.x * blockDim.x + threadIdx.x;
    if (i < half) {
        int4 a = __ldcs(&idx[i]);
        int4 b = __ldcs(&idx[i + half]);
        __stcs(&out[i],        make_float4((float)a.x, (float)a.y, (float)a.z, (float)a.w));
        __stcs(&out[i + half], make_float4((float)b.x, (float)b.y, (float)b.z, (float)b.w));
    }
}

__global__ void __launch_bounds__(256)
idx_cast_tail(const int* __restrict__ idx,
              float* __restrict__ out,
              int start, int n) {
    int i = start + blockIdx.x * blockDim.x + threadIdx.x;
    if (i < n) {
        out[i] = (float)idx[i];
    }
}

static inline int blocks_for(int n, int tpb) {
    return (int)(((long long)n + tpb - 1) / tpb);
}

extern "C" void kernel_launch(void* const* d_in, const int* in_sizes, int n_in,
                              void* d_out, int out_size) {
    const int*   indices = (const int*)d_in[0];
    const float* values  = (const float*)d_in[1];
    const int*   mask    = (const int*)d_in[2];

    const int n_idx = in_sizes[0];   // 2 * NNZ
    const int nnz   = in_sizes[1];   // NNZ

    const int TPB = 256;

    float* out_values = (float*)d_out;

    if (out_size >= n_idx + nnz) {
        float* out_idx = (float*)d_out;
        out_values = (float*)d_out + n_idx;

        int n4i   = n_idx / 4;       // full vec4 elements
        int halfi = n4i / 2;         // per-thread pair count
        if (halfi > 0) {
            idx_cast_vec4x2<<<blocks_for(halfi, TPB), TPB>>>(
                (const int4*)indices, (float4*)out_idx, halfi);
        }
        int donei = halfi * 2 * 4;   // elements covered by the vec kernel
        if (donei < n_idx) {
            idx_cast_tail<<<blocks_for(n_idx - donei, TPB), TPB>>>(
                indices, out_idx, donei, n_idx);
        }
    }

    int n4   = nnz / 4;
    int half = n4 / 2;
    if (half > 0) {
        dropout_vec4x2<<<blocks_for(half, TPB), TPB>>>(
            (const float4*)values, (const int4*)mask,
            (float4*)out_values, half);
    }
    int done = half * 2 * 4;
    if (done < nnz) {
        dropout_tail<<<blocks_for(nnz - done, TPB), TPB>>>(
            values, mask, out_values, done, nnz);
    }
}